// round 12
// baseline (speedup 1.0000x reference)
#include <cuda_runtime.h>
#include <cuda_bf16.h>
#include <cuda_fp16.h>
#include <cstdint>

// Problem constants
#define B_  4
#define L_  4096
#define D_  1024
#define H_  16
#define HD_ 64
#define P_  128
#define MAXLEN_ 4096
#define BH_ (B_ * H_)
#define M_FULL (B_ * L_)       // 16384
#define M_KV   (B_ * P_)       // 512

__device__ __forceinline__ uint32_t smem_u32(const void* p) {
    uint32_t a;
    asm("{ .reg .u64 t; cvta.to.shared.u64 t, %1; cvt.u32.u64 %0, t; }" : "=r"(a) : "l"(p));
    return a;
}
#define CP_ASYNC16(dst, src) \
    asm volatile("cp.async.cg.shared.global [%0], [%1], 16;" :: "r"(dst), "l"(src))
#define CP_COMMIT() asm volatile("cp.async.commit_group;" ::: "memory")
#define CP_WAIT1()  asm volatile("cp.async.wait_group 1;" ::: "memory")

#define LDSM_X4(R0, R1, R2, R3, A) \
    asm volatile("ldmatrix.sync.aligned.m8n8.x4.shared.b16 {%0,%1,%2,%3}, [%4];" \
        : "=r"(R0), "=r"(R1), "=r"(R2), "=r"(R3) : "r"(A))

#define MMAF16(D0, D1, D2, D3, A0, A1, A2, A3, B0, B1) \
    asm volatile("mma.sync.aligned.m16n8k16.row.col.f32.f16.f16.f32 " \
        "{%0,%1,%2,%3}, {%4,%5,%6,%7}, {%8,%9}, {%0,%1,%2,%3};" \
        : "+f"(D0), "+f"(D1), "+f"(D2), "+f"(D3) \
        : "r"(A0), "r"(A1), "r"(A2), "r"(A3), "r"(B0), "r"(B1))

// -------- scratch --------
__device__ __half g_xh [M_FULL * (size_t)D_];
__device__ __half g_As [M_FULL * (size_t)D_];
__device__ __half g_kvh[M_KV   * (size_t)D_];
__device__ __half g_Wq2[D_ * (size_t)D_];
__device__ __half g_Wkv[2 * D_ * (size_t)D_];   // [Wk rows | Wv rows]
__device__ __half g_Wo2[D_ * (size_t)D_];
__device__ __half g_Q [M_FULL * (size_t)D_];
__device__ float g_KV [M_KV * (size_t)(2 * D_)]; // cols 0..1023 K(rope), 1024..2047 V
__device__ float g_Kp[BH_ * P_ * HD_];
__device__ float g_Vp[BH_ * P_ * HD_];

// ===================================================================
// conv_all: one launch does xh, kvh (gathered), and the weight buffers.
// ===================================================================
#define SEG0 (M_FULL * 128)
#define SEG1 (SEG0 + M_KV * 128)
#define SEGW 131072
#define CONV_TOT (SEG1 + 4 * SEGW)

__global__ __launch_bounds__(256) void conv_all(
    const float* __restrict__ x,  const float* __restrict__ Wq,
    const float* __restrict__ Wk, const float* __restrict__ Wv,
    const float* __restrict__ Wo,
    __half* __restrict__ xh, __half* __restrict__ kvh,
    __half* __restrict__ Wq2, __half* __restrict__ Wkv, __half* __restrict__ Wo2)
{
    int i = blockIdx.x * 256 + threadIdx.x;
    if (i >= CONV_TOT) return;
    const float* src;
    __half* dst;
    int row, c;
    if (i < SEG0) {
        row = i >> 7; c = (i & 127) * 8;
        src = x; dst = xh;
    } else if (i < SEG1) {
        int r = i - SEG0;
        int drow = r >> 7; c = (r & 127) * 8;
        int b = drow >> 7, l = drow & 127;
        const float4* s = (const float4*)(x + ((size_t)b * L_ + l) * D_ + c);
        float4 f0 = s[0], f1 = s[1];
        __half2 h[4];
        h[0] = __floats2half2_rn(f0.x, f0.y);
        h[1] = __floats2half2_rn(f0.z, f0.w);
        h[2] = __floats2half2_rn(f1.x, f1.y);
        h[3] = __floats2half2_rn(f1.z, f1.w);
        *(uint4*)(kvh + (size_t)drow * D_ + c) = *(uint4*)h;
        return;
    } else {
        int r = i - SEG1;
        int seg = r / SEGW;
        int q = r - seg * SEGW;
        row = q >> 7; c = (q & 127) * 8;
        if (seg == 0)      { src = Wq; dst = Wq2; }
        else if (seg == 1) { src = Wk; dst = Wkv; }
        else if (seg == 2) { src = Wv; dst = Wkv + (size_t)D_ * D_; }
        else               { src = Wo; dst = Wo2; }
    }
    const float4* s = (const float4*)(src + (size_t)row * D_ + c);
    float4 f0 = s[0], f1 = s[1];
    __half2 h[4];
    h[0] = __floats2half2_rn(f0.x, f0.y);
    h[1] = __floats2half2_rn(f0.z, f0.w);
    h[2] = __floats2half2_rn(f1.x, f1.y);
    h[3] = __floats2half2_rn(f1.z, f1.w);
    *(uint4*)(dst + (size_t)row * D_ + c) = *(uint4*)h;
}

// ===================================================================
// fp16 mma GEMM (unchanged from R11)
// ===================================================================
#define BM 128
#define BN 128
#define BK 64
#define NSTG 3
#define NKC 16
#define OPA  (BM * 128)
#define STGB ((BM + BN) * 128)
#define GEMM_SMEM (NSTG * STGB)

__global__ __launch_bounds__(256, 2) void gemm_f16(
    const __half* __restrict__ A, const __half* __restrict__ W,
    float* __restrict__ Cf, __half* __restrict__ Ch, int NW,
    const float* __restrict__ rcos, const float* __restrict__ rsin,
    int lmask, int ropeN)
{
    extern __shared__ char dsm[];
    const uint32_t s0 = smem_u32(dsm);
    const int tid = threadIdx.x;
    const int wid = tid >> 5;
    const int lane = tid & 31;
    const int bx = blockIdx.x, by = blockIdx.y;

    const int lrow = tid >> 3;
    const int lch = tid & 7;
    const uint32_t sw0 = (uint32_t)(lrow * 128 + ((lch ^ (lrow & 7)) << 4));
    const char* aB = (const char*)(A + (size_t)(by * BM + lrow) * D_ + lch * 8);
    const char* wB = (const char*)(W + (size_t)(bx * BN + lrow) * D_ + lch * 8);
    const size_t RSTRIDE = (size_t)32 * D_ * 2;

    const int wm = wid >> 2;
    const int wn = wid & 3;
    const int lhalf = lane >> 4;

    uint32_t aro[4], bro[2];
    uint32_t arx[4], brx[2];
    #pragma unroll
    for (int mt = 0; mt < 4; ++mt) {
        int row = wm * 64 + mt * 16 + (lane & 15);
        aro[mt] = (uint32_t)(row * 128);
        arx[mt] = (uint32_t)(row & 7);
    }
    #pragma unroll
    for (int np = 0; np < 2; ++np) {
        int row = wn * 32 + np * 16 + (lane & 15);
        bro[np] = (uint32_t)(row * 128);
        brx[np] = (uint32_t)(row & 7);
    }

    float acc[4][4][4];
    #pragma unroll
    for (int i = 0; i < 4; ++i)
        #pragma unroll
        for (int j = 0; j < 4; ++j)
            #pragma unroll
            for (int q = 0; q < 4; ++q) acc[i][j][q] = 0.f;

    #pragma unroll
    for (int c = 0; c < NSTG - 1; ++c) {
        uint32_t sb = s0 + c * STGB;
        size_t off = (size_t)c * 128;
        #pragma unroll
        for (int j = 0; j < 4; ++j) {
            CP_ASYNC16(sb + sw0 + j * 4096,        aB + j * RSTRIDE + off);
            CP_ASYNC16(sb + OPA + sw0 + j * 4096,  wB + j * RSTRIDE + off);
        }
        CP_COMMIT();
    }

    int stage = 0;
    for (int kc = 0; kc < NKC; ++kc) {
        CP_WAIT1();
        __syncthreads();

        {
            int ldc = kc + NSTG - 1;
            if (ldc < NKC) {
                int ls = ldc % NSTG;
                uint32_t sb = s0 + ls * STGB;
                size_t off = (size_t)ldc * 128;
                #pragma unroll
                for (int j = 0; j < 4; ++j) {
                    CP_ASYNC16(sb + sw0 + j * 4096,       aB + j * RSTRIDE + off);
                    CP_ASYNC16(sb + OPA + sw0 + j * 4096, wB + j * RSTRIDE + off);
                }
            }
            CP_COMMIT();
        }

        const uint32_t ab = s0 + stage * STGB;
        const uint32_t bb = ab + OPA;
        #pragma unroll
        for (int ks = 0; ks < 4; ++ks) {
            const uint32_t ch = (uint32_t)(ks * 2 + lhalf);
            uint32_t a[4][4], b[4][2];
            #pragma unroll
            for (int mt = 0; mt < 4; ++mt) {
                uint32_t ad = ab + aro[mt] + ((ch ^ arx[mt]) << 4);
                LDSM_X4(a[mt][0], a[mt][1], a[mt][2], a[mt][3], ad);
            }
            #pragma unroll
            for (int np = 0; np < 2; ++np) {
                uint32_t bd = bb + bro[np] + ((ch ^ brx[np]) << 4);
                uint32_t r0, r1, r2, r3;
                LDSM_X4(r0, r1, r2, r3, bd);
                b[np * 2 + 0][0] = r0; b[np * 2 + 0][1] = r2;
                b[np * 2 + 1][0] = r1; b[np * 2 + 1][1] = r3;
            }
            #pragma unroll
            for (int mt = 0; mt < 4; ++mt)
                #pragma unroll
                for (int nt = 0; nt < 4; ++nt)
                    MMAF16(acc[mt][nt][0], acc[mt][nt][1], acc[mt][nt][2], acc[mt][nt][3],
                           a[mt][0], a[mt][1], a[mt][2], a[mt][3],
                           b[nt][0], b[nt][1]);
        }
        stage = (stage + 1 == NSTG) ? 0 : stage + 1;
    }

    const bool doRope = (rcos != nullptr) && (bx < ropeN);
    #pragma unroll
    for (int mt = 0; mt < 4; ++mt) {
        int row0 = by * BM + wm * 64 + mt * 16 + (lane >> 2);
        if (doRope) {
            int la = row0 & lmask;
            int lb = (row0 + 8) & lmask;
            #pragma unroll
            for (int nt = 0; nt < 4; ++nt) {
                int col = bx * BN + wn * 32 + nt * 8 + (lane & 3) * 2;
                int f = (col & 63) >> 1;
                float ca = rcos[la * 32 + f], sa = rsin[la * 32 + f];
                float cb = rcos[lb * 32 + f], sb = rsin[lb * 32 + f];
                float a0 = acc[mt][nt][0], a1 = acc[mt][nt][1];
                acc[mt][nt][0] = a0 * ca - a1 * sa;
                acc[mt][nt][1] = a0 * sa + a1 * ca;
                a0 = acc[mt][nt][2]; a1 = acc[mt][nt][3];
                acc[mt][nt][2] = a0 * cb - a1 * sb;
                acc[mt][nt][3] = a0 * sb + a1 * cb;
            }
        }
        #pragma unroll
        for (int nt = 0; nt < 4; ++nt) {
            int col = bx * BN + wn * 32 + nt * 8 + (lane & 3) * 2;
            if (Ch != nullptr) {
                *(__half2*)(Ch + (size_t)row0 * NW + col) =
                    __floats2half2_rn(acc[mt][nt][0], acc[mt][nt][1]);
                *(__half2*)(Ch + (size_t)(row0 + 8) * NW + col) =
                    __floats2half2_rn(acc[mt][nt][2], acc[mt][nt][3]);
            } else {
                *(float2*)(Cf + (size_t)row0 * NW + col) =
                    make_float2(acc[mt][nt][0], acc[mt][nt][1]);
                *(float2*)(Cf + (size_t)(row0 + 8) * NW + col) =
                    make_float2(acc[mt][nt][2], acc[mt][nt][3]);
            }
        }
    }
}

// ===================================================================
// K_proj/V_proj: block (p, b), 256 threads. Thread owns 8 contiguous
// cols of the 2048-wide fused KV row; mask stream picked by c<1024.
// Unroll 4 over l -> 8 float4 loads in flight.
// ===================================================================
__global__ __launch_bounds__(256) void proj_kernel(
    const float* __restrict__ KV,
    const float* __restrict__ kpm, const float* __restrict__ vpm,
    float* __restrict__ Kp, float* __restrict__ Vp)
{
    const int p = blockIdx.x;
    const int b = blockIdx.y;
    const int c = threadIdx.x * 8;                 // 0..2040
    const bool isK = (c < 1024);
    const float* mrow = (isK ? kpm : vpm) + (size_t)p * MAXLEN_;
    const float* base = KV + (size_t)b * P_ * (2 * D_) + c;

    float a0 = 0.f, a1 = 0.f, a2 = 0.f, a3 = 0.f;
    float a4 = 0.f, a5 = 0.f, a6 = 0.f, a7 = 0.f;

    int l = 0;
    const int lim = p + 1;
    #pragma unroll 1
    for (; l + 4 <= lim; l += 4) {
        #pragma unroll
        for (int u = 0; u < 4; ++u) {
            float m = mrow[l + u];
            const float4* r = (const float4*)(base + (size_t)(l + u) * (2 * D_));
            float4 v0 = r[0], v1 = r[1];
            a0 += m * v0.x; a1 += m * v0.y; a2 += m * v0.z; a3 += m * v0.w;
            a4 += m * v1.x; a5 += m * v1.y; a6 += m * v1.z; a7 += m * v1.w;
        }
    }
    for (; l < lim; ++l) {
        float m = mrow[l];
        const float4* r = (const float4*)(base + (size_t)l * (2 * D_));
        float4 v0 = r[0], v1 = r[1];
        a0 += m * v0.x; a1 += m * v0.y; a2 += m * v0.z; a3 += m * v0.w;
        a4 += m * v1.x; a5 += m * v1.y; a6 += m * v1.z; a7 += m * v1.w;
    }

    // store into Kp/Vp layout [bh][p][d]
    int cc = isK ? c : c - 1024;
    int h = cc >> 6;
    int d = cc & 63;
    float* outp = (isK ? Kp : Vp) + (((size_t)(b * H_ + h) * P_ + p) * HD_ + d);
    *(float4*)(outp)     = make_float4(a0, a1, a2, a3);
    *(float4*)(outp + 4) = make_float4(a4, a5, a6, a7);
}

// ===================================================================
// Attention: 4 Q-tiles (512 l's) per CTA, K/V smem loaded once.
// ===================================================================
#define QH_OFF   0
#define KH_OFF   18432
#define VT_OFF   36864
#define PH_OFF   54272
#define REDM_OFF 89088
#define REDS_OFF 91136
#define ATT_SMEM 93184
#define ATT_TILES 4

__global__ __launch_bounds__(256) void attn_mma(
    const __half* __restrict__ Q, const float* __restrict__ Kp,
    const float* __restrict__ Vp, __half* __restrict__ As)
{
    extern __shared__ char sm[];
    const uint32_t s0 = smem_u32(sm);
    const int tid = threadIdx.x;
    const int lane = tid & 31;
    const int wid = tid >> 5;
    const int wm = wid >> 2;
    const int wn = wid & 3;
    const int lhalf = lane >> 4;
    const int bh = blockIdx.y;
    const int b = bh >> 4, h = bh & 15;

    const float* kg = Kp + (size_t)bh * P_ * HD_;
    const float* vg = Vp + (size_t)bh * P_ * HD_;
    #pragma unroll
    for (int t = 0; t < 8; ++t) {
        int e = t * 256 + tid;
        int r = e >> 4;
        int d0 = (e & 15) * 4;
        float4 k = *(const float4*)(kg + r * HD_ + d0);
        __half2* dk = (__half2*)(sm + KH_OFF + (r * 72 + d0) * 2);
        dk[0] = __floats2half2_rn(k.x, k.y);
        dk[1] = __floats2half2_rn(k.z, k.w);
        float4 w = *(const float4*)(vg + r * HD_ + d0);
        __half* vt = (__half*)(sm + VT_OFF);
        vt[(d0 + 0) * 136 + r] = __float2half_rn(w.x);
        vt[(d0 + 1) * 136 + r] = __float2half_rn(w.y);
        vt[(d0 + 2) * 136 + r] = __float2half_rn(w.z);
        vt[(d0 + 3) * 136 + r] = __float2half_rn(w.w);
    }

    float* redm = (float*)(sm + REDM_OFF);
    float* reds = (float*)(sm + REDS_OFF);

    for (int t2 = 0; t2 < ATT_TILES; ++t2) {
        const int l0 = blockIdx.x * (128 * ATT_TILES) + t2 * 128;

        const __half* qg = Q + ((size_t)(b * L_ + l0)) * D_ + h * HD_;
        #pragma unroll
        for (int t = 0; t < 4; ++t) {
            int e = t * 256 + tid;
            int r = e >> 3;
            int c = (e & 7) * 8;
            uint4 v = *(const uint4*)(qg + (size_t)r * D_ + c);
            *(uint4*)(sm + QH_OFF + (r * 72 + c) * 2) = v;
        }
        __syncthreads();

        float sc[4][4][4];
        #pragma unroll
        for (int i = 0; i < 4; ++i)
            #pragma unroll
            for (int j = 0; j < 4; ++j)
                #pragma unroll
                for (int q = 0; q < 4; ++q) sc[i][j][q] = 0.f;

        #pragma unroll
        for (int kc = 0; kc < 4; ++kc) {
            uint32_t a[4][4], bfr[4][2];
            #pragma unroll
            for (int mt = 0; mt < 4; ++mt) {
                uint32_t ad = s0 + QH_OFF + ((wm * 64 + mt * 16 + (lane & 15)) * 72) * 2
                            + (kc * 2 + lhalf) * 16;
                LDSM_X4(a[mt][0], a[mt][1], a[mt][2], a[mt][3], ad);
            }
            #pragma unroll
            for (int np = 0; np < 2; ++np) {
                uint32_t bd = s0 + KH_OFF + ((wn * 32 + np * 16 + (lane & 15)) * 72) * 2
                            + (kc * 2 + lhalf) * 16;
                uint32_t r0, r1, r2, r3;
                LDSM_X4(r0, r1, r2, r3, bd);
                bfr[np * 2 + 0][0] = r0; bfr[np * 2 + 0][1] = r2;
                bfr[np * 2 + 1][0] = r1; bfr[np * 2 + 1][1] = r3;
            }
            #pragma unroll
            for (int mt = 0; mt < 4; ++mt)
                #pragma unroll
                for (int nt = 0; nt < 4; ++nt)
                    MMAF16(sc[mt][nt][0], sc[mt][nt][1], sc[mt][nt][2], sc[mt][nt][3],
                           a[mt][0], a[mt][1], a[mt][2], a[mt][3],
                           bfr[nt][0], bfr[nt][1]);
        }

        const bool dom = (blockIdx.x == 0) && (t2 == 0);
        #pragma unroll
        for (int mt = 0; mt < 4; ++mt) {
            int r0 = wm * 64 + mt * 16 + (lane >> 2);
            #pragma unroll
            for (int nt = 0; nt < 4; ++nt) {
                int c0 = wn * 32 + nt * 8 + (lane & 3) * 2;
                #pragma unroll
                for (int q = 0; q < 4; ++q) {
                    sc[mt][nt][q] *= 0.125f;
                    if (dom) {
                        int rr = r0 + ((q >= 2) ? 8 : 0);
                        int cc = c0 + (q & 1);
                        if (cc > rr) sc[mt][nt][q] = -1e30f;
                    }
                }
            }
        }

        #pragma unroll
        for (int mt = 0; mt < 4; ++mt) {
            float mlo = -1e30f, mhi = -1e30f;
            #pragma unroll
            for (int nt = 0; nt < 4; ++nt) {
                mlo = fmaxf(mlo, fmaxf(sc[mt][nt][0], sc[mt][nt][1]));
                mhi = fmaxf(mhi, fmaxf(sc[mt][nt][2], sc[mt][nt][3]));
            }
            #pragma unroll
            for (int o = 1; o <= 2; o <<= 1) {
                mlo = fmaxf(mlo, __shfl_xor_sync(0xffffffffu, mlo, o));
                mhi = fmaxf(mhi, __shfl_xor_sync(0xffffffffu, mhi, o));
            }
            if ((lane & 3) == 0) {
                int r0 = wm * 64 + mt * 16 + (lane >> 2);
                redm[wn * 128 + r0] = mlo;
                redm[wn * 128 + r0 + 8] = mhi;
            }
        }
        __syncthreads();

        #pragma unroll
        for (int mt = 0; mt < 4; ++mt) {
            int r0 = wm * 64 + mt * 16 + (lane >> 2);
            float mlo = fmaxf(fmaxf(redm[r0], redm[128 + r0]),
                              fmaxf(redm[256 + r0], redm[384 + r0]));
            int r1 = r0 + 8;
            float mhi = fmaxf(fmaxf(redm[r1], redm[128 + r1]),
                              fmaxf(redm[256 + r1], redm[384 + r1]));
            float slo = 0.f, shi = 0.f;
            #pragma unroll
            for (int nt = 0; nt < 4; ++nt) {
                sc[mt][nt][0] = __expf(sc[mt][nt][0] - mlo);
                sc[mt][nt][1] = __expf(sc[mt][nt][1] - mlo);
                sc[mt][nt][2] = __expf(sc[mt][nt][2] - mhi);
                sc[mt][nt][3] = __expf(sc[mt][nt][3] - mhi);
                slo += sc[mt][nt][0] + sc[mt][nt][1];
                shi += sc[mt][nt][2] + sc[mt][nt][3];
            }
            #pragma unroll
            for (int o = 1; o <= 2; o <<= 1) {
                slo += __shfl_xor_sync(0xffffffffu, slo, o);
                shi += __shfl_xor_sync(0xffffffffu, shi, o);
            }
            if ((lane & 3) == 0) {
                reds[wn * 128 + r0] = slo;
                reds[wn * 128 + r0 + 8] = shi;
            }
        }
        __syncthreads();

        #pragma unroll
        for (int mt = 0; mt < 4; ++mt) {
            int r0 = wm * 64 + mt * 16 + (lane >> 2);
            int r1 = r0 + 8;
            float ilo = __frcp_rn(reds[r0] + reds[128 + r0] + reds[256 + r0] + reds[384 + r0]);
            float ihi = __frcp_rn(reds[r1] + reds[128 + r1] + reds[256 + r1] + reds[384 + r1]);
            #pragma unroll
            for (int nt = 0; nt < 4; ++nt) {
                int c0 = wn * 32 + nt * 8 + (lane & 3) * 2;
                *(__half2*)(sm + PH_OFF + (r0 * 136 + c0) * 2) =
                    __floats2half2_rn(sc[mt][nt][0] * ilo, sc[mt][nt][1] * ilo);
                *(__half2*)(sm + PH_OFF + (r1 * 136 + c0) * 2) =
                    __floats2half2_rn(sc[mt][nt][2] * ihi, sc[mt][nt][3] * ihi);
            }
        }
        __syncthreads();

        float oc[4][2][4];
        #pragma unroll
        for (int i = 0; i < 4; ++i)
            #pragma unroll
            for (int j = 0; j < 2; ++j)
                #pragma unroll
                for (int q = 0; q < 4; ++q) oc[i][j][q] = 0.f;

        #pragma unroll
        for (int kc = 0; kc < 8; ++kc) {
            uint32_t a[4][4], bfr[2][2];
            #pragma unroll
            for (int mt = 0; mt < 4; ++mt) {
                uint32_t ad = s0 + PH_OFF + ((wm * 64 + mt * 16 + (lane & 15)) * 136) * 2
                            + (kc * 2 + lhalf) * 16;
                LDSM_X4(a[mt][0], a[mt][1], a[mt][2], a[mt][3], ad);
            }
            {
                uint32_t bd = s0 + VT_OFF + ((wn * 16 + (lane & 15)) * 136) * 2
                            + (kc * 2 + lhalf) * 16;
                uint32_t r0, r1, r2, r3;
                LDSM_X4(r0, r1, r2, r3, bd);
                bfr[0][0] = r0; bfr[0][1] = r2;
                bfr[1][0] = r1; bfr[1][1] = r3;
            }
            #pragma unroll
            for (int mt = 0; mt < 4; ++mt)
                #pragma unroll
                for (int nt = 0; nt < 2; ++nt)
                    MMAF16(oc[mt][nt][0], oc[mt][nt][1], oc[mt][nt][2], oc[mt][nt][3],
                           a[mt][0], a[mt][1], a[mt][2], a[mt][3],
                           bfr[nt][0], bfr[nt][1]);
        }

        #pragma unroll
        for (int mt = 0; mt < 4; ++mt) {
            int r0 = wm * 64 + mt * 16 + (lane >> 2);
            #pragma unroll
            for (int nt = 0; nt < 2; ++nt) {
                int cd = wn * 16 + nt * 8 + (lane & 3) * 2;
                int gcol = h * HD_ + cd;
                *(__half2*)(As + (size_t)(b * L_ + l0 + r0) * D_ + gcol) =
                    __floats2half2_rn(oc[mt][nt][0], oc[mt][nt][1]);
                *(__half2*)(As + (size_t)(b * L_ + l0 + r0 + 8) * D_ + gcol) =
                    __floats2half2_rn(oc[mt][nt][2], oc[mt][nt][3]);
            }
        }
        __syncthreads();
    }
}

// ===================================================================
extern "C" void kernel_launch(void* const* d_in, const int* in_sizes, int n_in,
                              void* d_out, int out_size)
{
    const float* x   = (const float*)d_in[0];
    const float* fc  = (const float*)d_in[1];
    const float* fs  = (const float*)d_in[2];
    const float* Wq  = (const float*)d_in[3];
    const float* Wk  = (const float*)d_in[4];
    const float* Wv  = (const float*)d_in[5];
    const float* Wo  = (const float*)d_in[6];
    const float* kpm = (const float*)d_in[7];
    const float* vpm = (const float*)d_in[8];
    float* out = (float*)d_out;

    __half *xh, *As, *kvh, *Wq2, *Wkv, *Wo2, *Qh;
    float *KV, *Kpp, *Vpp;
    cudaGetSymbolAddress((void**)&xh,  g_xh);
    cudaGetSymbolAddress((void**)&As,  g_As);
    cudaGetSymbolAddress((void**)&kvh, g_kvh);
    cudaGetSymbolAddress((void**)&Wq2, g_Wq2);
    cudaGetSymbolAddress((void**)&Wkv, g_Wkv);
    cudaGetSymbolAddress((void**)&Wo2, g_Wo2);
    cudaGetSymbolAddress((void**)&Qh,  g_Q);
    cudaGetSymbolAddress((void**)&KV,  g_KV);
    cudaGetSymbolAddress((void**)&Kpp, g_Kp);
    cudaGetSymbolAddress((void**)&Vpp, g_Vp);

    cudaFuncSetAttribute(gemm_f16, cudaFuncAttributeMaxDynamicSharedMemorySize, GEMM_SMEM);
    cudaFuncSetAttribute(attn_mma, cudaFuncAttributeMaxDynamicSharedMemorySize, ATT_SMEM);

    // one conversion launch
    conv_all<<<(CONV_TOT + 255) / 256, 256>>>(x, Wq, Wk, Wv, Wo, xh, kvh, Wq2, Wkv, Wo2);

    // Q projection (rope on all tiles, fp16 out)
    gemm_f16<<<dim3(D_ / BN, M_FULL / BM), 256, GEMM_SMEM>>>(
        xh, Wq2, nullptr, Qh, D_, fc, fs, L_ - 1, D_ / BN);

    // fused K+V projection (rope on K half only)
    gemm_f16<<<dim3(2 * D_ / BN, M_KV / BM), 256, GEMM_SMEM>>>(
        kvh, Wkv, KV, nullptr, 2 * D_, fc, fs, P_ - 1, D_ / BN);

    // low-rank projections (tril-masked), vectorized 8-wide
    proj_kernel<<<dim3(P_, B_), 256>>>(KV, kpm, vpm, Kpp, Vpp);

    // attention (4 tiles per CTA)
    attn_mma<<<dim3(L_ / (128 * ATT_TILES), BH_), 256, ATT_SMEM>>>(Qh, Kpp, Vpp, As);

    // final projection (fp32 out)
    gemm_f16<<<dim3(D_ / BN, M_FULL / BM), 256, GEMM_SMEM>>>(
        As, Wo2, out, nullptr, D_, nullptr, nullptr, 0, 0);
}

// round 13
// speedup vs baseline: 1.0514x; 1.0514x over previous
#include <cuda_runtime.h>
#include <cuda_bf16.h>
#include <cuda_fp16.h>
#include <cstdint>

// Problem constants
#define B_  4
#define L_  4096
#define D_  1024
#define H_  16
#define HD_ 64
#define P_  128
#define MAXLEN_ 4096
#define BH_ (B_ * H_)
#define M_FULL (B_ * L_)       // 16384
#define M_KV   (B_ * P_)       // 512

__device__ __forceinline__ uint32_t smem_u32(const void* p) {
    uint32_t a;
    asm("{ .reg .u64 t; cvta.to.shared.u64 t, %1; cvt.u32.u64 %0, t; }" : "=r"(a) : "l"(p));
    return a;
}
#define CP_ASYNC16(dst, src) \
    asm volatile("cp.async.cg.shared.global [%0], [%1], 16;" :: "r"(dst), "l"(src))
#define CP_COMMIT() asm volatile("cp.async.commit_group;" ::: "memory")
#define CP_WAIT1()  asm volatile("cp.async.wait_group 1;" ::: "memory")

#define LDSM_X4(R0, R1, R2, R3, A) \
    asm volatile("ldmatrix.sync.aligned.m8n8.x4.shared.b16 {%0,%1,%2,%3}, [%4];" \
        : "=r"(R0), "=r"(R1), "=r"(R2), "=r"(R3) : "r"(A))

#define MMAF16(D0, D1, D2, D3, A0, A1, A2, A3, B0, B1) \
    asm volatile("mma.sync.aligned.m16n8k16.row.col.f32.f16.f16.f32 " \
        "{%0,%1,%2,%3}, {%4,%5,%6,%7}, {%8,%9}, {%0,%1,%2,%3};" \
        : "+f"(D0), "+f"(D1), "+f"(D2), "+f"(D3) \
        : "r"(A0), "r"(A1), "r"(A2), "r"(A3), "r"(B0), "r"(B1))

// -------- scratch --------
__device__ __half g_xh [M_FULL * (size_t)D_];
__device__ __half g_As [M_FULL * (size_t)D_];
__device__ __half g_kvh[M_KV   * (size_t)D_];
__device__ __half g_Wq2[D_ * (size_t)D_];
__device__ __half g_Wkv[2 * D_ * (size_t)D_];   // [Wk rows | Wv rows]
__device__ __half g_Wo2[D_ * (size_t)D_];
__device__ __half g_Q [M_FULL * (size_t)D_];
__device__ float g_KV [M_KV * (size_t)(2 * D_)]; // cols 0..1023 K(rope), 1024..2047 V
__device__ __half g_Kp[BH_ * P_ * HD_];          // fp16 now
__device__ __half g_Vp[BH_ * P_ * HD_];

// ===================================================================
// conv_all: one launch does xh, kvh (gathered), and the weight buffers.
// ===================================================================
#define SEG0 (M_FULL * 128)
#define SEG1 (SEG0 + M_KV * 128)
#define SEGW 131072
#define CONV_TOT (SEG1 + 4 * SEGW)

__global__ __launch_bounds__(256) void conv_all(
    const float* __restrict__ x,  const float* __restrict__ Wq,
    const float* __restrict__ Wk, const float* __restrict__ Wv,
    const float* __restrict__ Wo,
    __half* __restrict__ xh, __half* __restrict__ kvh,
    __half* __restrict__ Wq2, __half* __restrict__ Wkv, __half* __restrict__ Wo2)
{
    int i = blockIdx.x * 256 + threadIdx.x;
    if (i >= CONV_TOT) return;
    const float* src;
    __half* dst;
    int row, c;
    if (i < SEG0) {
        row = i >> 7; c = (i & 127) * 8;
        src = x; dst = xh;
    } else if (i < SEG1) {
        int r = i - SEG0;
        int drow = r >> 7; c = (r & 127) * 8;
        int b = drow >> 7, l = drow & 127;
        const float4* s = (const float4*)(x + ((size_t)b * L_ + l) * D_ + c);
        float4 f0 = s[0], f1 = s[1];
        __half2 h[4];
        h[0] = __floats2half2_rn(f0.x, f0.y);
        h[1] = __floats2half2_rn(f0.z, f0.w);
        h[2] = __floats2half2_rn(f1.x, f1.y);
        h[3] = __floats2half2_rn(f1.z, f1.w);
        *(uint4*)(kvh + (size_t)drow * D_ + c) = *(uint4*)h;
        return;
    } else {
        int r = i - SEG1;
        int seg = r / SEGW;
        int q = r - seg * SEGW;
        row = q >> 7; c = (q & 127) * 8;
        if (seg == 0)      { src = Wq; dst = Wq2; }
        else if (seg == 1) { src = Wk; dst = Wkv; }
        else if (seg == 2) { src = Wv; dst = Wkv + (size_t)D_ * D_; }
        else               { src = Wo; dst = Wo2; }
    }
    const float4* s = (const float4*)(src + (size_t)row * D_ + c);
    float4 f0 = s[0], f1 = s[1];
    __half2 h[4];
    h[0] = __floats2half2_rn(f0.x, f0.y);
    h[1] = __floats2half2_rn(f0.z, f0.w);
    h[2] = __floats2half2_rn(f1.x, f1.y);
    h[3] = __floats2half2_rn(f1.z, f1.w);
    *(uint4*)(dst + (size_t)row * D_ + c) = *(uint4*)h;
}

// ===================================================================
// fp16 mma GEMM (unchanged)
// ===================================================================
#define BM 128
#define BN 128
#define BK 64
#define NSTG 3
#define NKC 16
#define OPA  (BM * 128)
#define STGB ((BM + BN) * 128)
#define GEMM_SMEM (NSTG * STGB)

__global__ __launch_bounds__(256, 2) void gemm_f16(
    const __half* __restrict__ A, const __half* __restrict__ W,
    float* __restrict__ Cf, __half* __restrict__ Ch, int NW,
    const float* __restrict__ rcos, const float* __restrict__ rsin,
    int lmask, int ropeN)
{
    extern __shared__ char dsm[];
    const uint32_t s0 = smem_u32(dsm);
    const int tid = threadIdx.x;
    const int wid = tid >> 5;
    const int lane = tid & 31;
    const int bx = blockIdx.x, by = blockIdx.y;

    const int lrow = tid >> 3;
    const int lch = tid & 7;
    const uint32_t sw0 = (uint32_t)(lrow * 128 + ((lch ^ (lrow & 7)) << 4));
    const char* aB = (const char*)(A + (size_t)(by * BM + lrow) * D_ + lch * 8);
    const char* wB = (const char*)(W + (size_t)(bx * BN + lrow) * D_ + lch * 8);
    const size_t RSTRIDE = (size_t)32 * D_ * 2;

    const int wm = wid >> 2;
    const int wn = wid & 3;
    const int lhalf = lane >> 4;

    uint32_t aro[4], bro[2];
    uint32_t arx[4], brx[2];
    #pragma unroll
    for (int mt = 0; mt < 4; ++mt) {
        int row = wm * 64 + mt * 16 + (lane & 15);
        aro[mt] = (uint32_t)(row * 128);
        arx[mt] = (uint32_t)(row & 7);
    }
    #pragma unroll
    for (int np = 0; np < 2; ++np) {
        int row = wn * 32 + np * 16 + (lane & 15);
        bro[np] = (uint32_t)(row * 128);
        brx[np] = (uint32_t)(row & 7);
    }

    float acc[4][4][4];
    #pragma unroll
    for (int i = 0; i < 4; ++i)
        #pragma unroll
        for (int j = 0; j < 4; ++j)
            #pragma unroll
            for (int q = 0; q < 4; ++q) acc[i][j][q] = 0.f;

    #pragma unroll
    for (int c = 0; c < NSTG - 1; ++c) {
        uint32_t sb = s0 + c * STGB;
        size_t off = (size_t)c * 128;
        #pragma unroll
        for (int j = 0; j < 4; ++j) {
            CP_ASYNC16(sb + sw0 + j * 4096,        aB + j * RSTRIDE + off);
            CP_ASYNC16(sb + OPA + sw0 + j * 4096,  wB + j * RSTRIDE + off);
        }
        CP_COMMIT();
    }

    int stage = 0;
    for (int kc = 0; kc < NKC; ++kc) {
        CP_WAIT1();
        __syncthreads();

        {
            int ldc = kc + NSTG - 1;
            if (ldc < NKC) {
                int ls = ldc % NSTG;
                uint32_t sb = s0 + ls * STGB;
                size_t off = (size_t)ldc * 128;
                #pragma unroll
                for (int j = 0; j < 4; ++j) {
                    CP_ASYNC16(sb + sw0 + j * 4096,       aB + j * RSTRIDE + off);
                    CP_ASYNC16(sb + OPA + sw0 + j * 4096, wB + j * RSTRIDE + off);
                }
            }
            CP_COMMIT();
        }

        const uint32_t ab = s0 + stage * STGB;
        const uint32_t bb = ab + OPA;
        #pragma unroll
        for (int ks = 0; ks < 4; ++ks) {
            const uint32_t ch = (uint32_t)(ks * 2 + lhalf);
            uint32_t a[4][4], b[4][2];
            #pragma unroll
            for (int mt = 0; mt < 4; ++mt) {
                uint32_t ad = ab + aro[mt] + ((ch ^ arx[mt]) << 4);
                LDSM_X4(a[mt][0], a[mt][1], a[mt][2], a[mt][3], ad);
            }
            #pragma unroll
            for (int np = 0; np < 2; ++np) {
                uint32_t bd = bb + bro[np] + ((ch ^ brx[np]) << 4);
                uint32_t r0, r1, r2, r3;
                LDSM_X4(r0, r1, r2, r3, bd);
                b[np * 2 + 0][0] = r0; b[np * 2 + 0][1] = r2;
                b[np * 2 + 1][0] = r1; b[np * 2 + 1][1] = r3;
            }
            #pragma unroll
            for (int mt = 0; mt < 4; ++mt)
                #pragma unroll
                for (int nt = 0; nt < 4; ++nt)
                    MMAF16(acc[mt][nt][0], acc[mt][nt][1], acc[mt][nt][2], acc[mt][nt][3],
                           a[mt][0], a[mt][1], a[mt][2], a[mt][3],
                           b[nt][0], b[nt][1]);
        }
        stage = (stage + 1 == NSTG) ? 0 : stage + 1;
    }

    const bool doRope = (rcos != nullptr) && (bx < ropeN);
    #pragma unroll
    for (int mt = 0; mt < 4; ++mt) {
        int row0 = by * BM + wm * 64 + mt * 16 + (lane >> 2);
        if (doRope) {
            int la = row0 & lmask;
            int lb = (row0 + 8) & lmask;
            #pragma unroll
            for (int nt = 0; nt < 4; ++nt) {
                int col = bx * BN + wn * 32 + nt * 8 + (lane & 3) * 2;
                int f = (col & 63) >> 1;
                float ca = rcos[la * 32 + f], sa = rsin[la * 32 + f];
                float cb = rcos[lb * 32 + f], sb = rsin[lb * 32 + f];
                float a0 = acc[mt][nt][0], a1 = acc[mt][nt][1];
                acc[mt][nt][0] = a0 * ca - a1 * sa;
                acc[mt][nt][1] = a0 * sa + a1 * ca;
                a0 = acc[mt][nt][2]; a1 = acc[mt][nt][3];
                acc[mt][nt][2] = a0 * cb - a1 * sb;
                acc[mt][nt][3] = a0 * sb + a1 * cb;
            }
        }
        #pragma unroll
        for (int nt = 0; nt < 4; ++nt) {
            int col = bx * BN + wn * 32 + nt * 8 + (lane & 3) * 2;
            if (Ch != nullptr) {
                *(__half2*)(Ch + (size_t)row0 * NW + col) =
                    __floats2half2_rn(acc[mt][nt][0], acc[mt][nt][1]);
                *(__half2*)(Ch + (size_t)(row0 + 8) * NW + col) =
                    __floats2half2_rn(acc[mt][nt][2], acc[mt][nt][3]);
            } else {
                *(float2*)(Cf + (size_t)row0 * NW + col) =
                    make_float2(acc[mt][nt][0], acc[mt][nt][1]);
                *(float2*)(Cf + (size_t)(row0 + 8) * NW + col) =
                    make_float2(acc[mt][nt][2], acc[mt][nt][3]);
            }
        }
    }
}

// ===================================================================
// proj_tc: O[128p,128c] = (mask*tril)[128,128] @ KV_b[128l, c-slice]
// via tensor cores. grid (16 c-tiles, 4 b), 256 thr, fp16 out.
// ===================================================================
#define PJ_MS 0                 // mask tile  128 x 136 half = 34816 B
#define PJ_BS 34816             // KV^T tile  128 x 136 half
#define PJ_SMEM 69632

__global__ __launch_bounds__(256) void proj_tc(
    const float* __restrict__ KV,
    const float* __restrict__ kpm, const float* __restrict__ vpm,
    __half* __restrict__ Kp, __half* __restrict__ Vp)
{
    extern __shared__ char sm[];
    const uint32_t s0 = smem_u32(sm);
    const int tid = threadIdx.x;
    const int lane = tid & 31;
    const int wid = tid >> 5;
    const int wm = wid >> 2;
    const int wn = wid & 3;
    const int lhalf = lane >> 4;
    const int ct = blockIdx.x;        // 0..15
    const int b = blockIdx.y;
    const bool isK = (ct < 8);
    const int c0 = ct * 128;          // global col in KV row

    const float* mask = isK ? kpm : vpm;
    __half* ms = (__half*)(sm + PJ_MS);
    __half* bs = (__half*)(sm + PJ_BS);

    // mask tile with tril applied: ms[p][l]
    for (int i = tid; i < 128 * 128; i += 256) {
        int p = i >> 7, l = i & 127;
        float m = (l <= p) ? mask[(size_t)p * MAXLEN_ + l] : 0.f;
        ms[p * 136 + l] = __float2half_rn(m);
    }
    // KV^T tile: bs[cc][l] = KV[b, l, c0+cc]
    for (int i = tid; i < 128 * 128; i += 256) {
        int l = i >> 7, cc = i & 127;
        float v = KV[(size_t)b * P_ * (2 * D_) + (size_t)l * (2 * D_) + c0 + cc];
        bs[cc * 136 + l] = __float2half_rn(v);
    }
    __syncthreads();

    float acc[4][4][4];
    #pragma unroll
    for (int i = 0; i < 4; ++i)
        #pragma unroll
        for (int j = 0; j < 4; ++j)
            #pragma unroll
            for (int q = 0; q < 4; ++q) acc[i][j][q] = 0.f;

    #pragma unroll
    for (int kc = 0; kc < 8; ++kc) {
        uint32_t a[4][4], bfr[4][2];
        #pragma unroll
        for (int mt = 0; mt < 4; ++mt) {
            uint32_t ad = s0 + PJ_MS + ((wm * 64 + mt * 16 + (lane & 15)) * 136) * 2
                        + (kc * 2 + lhalf) * 16;
            LDSM_X4(a[mt][0], a[mt][1], a[mt][2], a[mt][3], ad);
        }
        #pragma unroll
        for (int np = 0; np < 2; ++np) {
            uint32_t bd = s0 + PJ_BS + ((wn * 32 + np * 16 + (lane & 15)) * 136) * 2
                        + (kc * 2 + lhalf) * 16;
            uint32_t r0, r1, r2, r3;
            LDSM_X4(r0, r1, r2, r3, bd);
            bfr[np * 2 + 0][0] = r0; bfr[np * 2 + 0][1] = r2;
            bfr[np * 2 + 1][0] = r1; bfr[np * 2 + 1][1] = r3;
        }
        #pragma unroll
        for (int mt = 0; mt < 4; ++mt)
            #pragma unroll
            for (int nt = 0; nt < 4; ++nt)
                MMAF16(acc[mt][nt][0], acc[mt][nt][1], acc[mt][nt][2], acc[mt][nt][3],
                       a[mt][0], a[mt][1], a[mt][2], a[mt][3],
                       bfr[nt][0], bfr[nt][1]);
    }

    // epilogue: out[(b*16+h)*128 + p][d] fp16, h/d from within-half col
    __half* outb = isK ? Kp : Vp;
    const int chbase = isK ? c0 : c0 - 1024;
    #pragma unroll
    for (int mt = 0; mt < 4; ++mt) {
        int p0 = wm * 64 + mt * 16 + (lane >> 2);
        #pragma unroll
        for (int nt = 0; nt < 4; ++nt) {
            int ch = chbase + wn * 32 + nt * 8 + (lane & 3) * 2;
            int h = ch >> 6, d = ch & 63;
            __half* dst0 = outb + (((size_t)(b * H_ + h) * P_ + p0) * HD_ + d);
            __half* dst1 = outb + (((size_t)(b * H_ + h) * P_ + p0 + 8) * HD_ + d);
            *(__half2*)dst0 = __floats2half2_rn(acc[mt][nt][0], acc[mt][nt][1]);
            *(__half2*)dst1 = __floats2half2_rn(acc[mt][nt][2], acc[mt][nt][3]);
        }
    }
}

// ===================================================================
// Attention: 4 Q-tiles per CTA, K/V (fp16) smem loaded once.
// ===================================================================
#define QH_OFF   0
#define KH_OFF   18432
#define VT_OFF   36864
#define PH_OFF   54272
#define REDM_OFF 89088
#define REDS_OFF 91136
#define ATT_SMEM 93184
#define ATT_TILES 4

__global__ __launch_bounds__(256) void attn_mma(
    const __half* __restrict__ Q, const __half* __restrict__ Kp,
    const __half* __restrict__ Vp, __half* __restrict__ As)
{
    extern __shared__ char sm[];
    const uint32_t s0 = smem_u32(sm);
    const int tid = threadIdx.x;
    const int lane = tid & 31;
    const int wid = tid >> 5;
    const int wm = wid >> 2;
    const int wn = wid & 3;
    const int lhalf = lane >> 4;
    const int bh = blockIdx.y;
    const int b = bh >> 4, h = bh & 15;

    const __half* kg = Kp + (size_t)bh * P_ * HD_;
    const __half* vg = Vp + (size_t)bh * P_ * HD_;
    // K: plain copy 128 rows x 64 halfs into stride-72 rows
    #pragma unroll
    for (int t = 0; t < 4; ++t) {
        int e = t * 256 + tid;
        int r = e >> 3;
        int ch = (e & 7) * 8;
        *(uint4*)(sm + KH_OFF + (r * 72 + ch) * 2) = *(const uint4*)(kg + r * HD_ + ch);
    }
    // V: scalar transpose vt[d][p] from fp16 [p][d]
    #pragma unroll
    for (int t = 0; t < 4; ++t) {
        int e = t * 256 + tid;
        int r = e >> 3;
        int d0 = (e & 7) * 8;
        uint4 v = *(const uint4*)(vg + r * HD_ + d0);
        const __half* hv = (const __half*)&v;
        __half* vt = (__half*)(sm + VT_OFF);
        #pragma unroll
        for (int j = 0; j < 8; ++j) vt[(d0 + j) * 136 + r] = hv[j];
    }

    float* redm = (float*)(sm + REDM_OFF);
    float* reds = (float*)(sm + REDS_OFF);

    for (int t2 = 0; t2 < ATT_TILES; ++t2) {
        const int l0 = blockIdx.x * (128 * ATT_TILES) + t2 * 128;

        const __half* qg = Q + ((size_t)(b * L_ + l0)) * D_ + h * HD_;
        #pragma unroll
        for (int t = 0; t < 4; ++t) {
            int e = t * 256 + tid;
            int r = e >> 3;
            int c = (e & 7) * 8;
            uint4 v = *(const uint4*)(qg + (size_t)r * D_ + c);
            *(uint4*)(sm + QH_OFF + (r * 72 + c) * 2) = v;
        }
        __syncthreads();

        float sc[4][4][4];
        #pragma unroll
        for (int i = 0; i < 4; ++i)
            #pragma unroll
            for (int j = 0; j < 4; ++j)
                #pragma unroll
                for (int q = 0; q < 4; ++q) sc[i][j][q] = 0.f;

        #pragma unroll
        for (int kc = 0; kc < 4; ++kc) {
            uint32_t a[4][4], bfr[4][2];
            #pragma unroll
            for (int mt = 0; mt < 4; ++mt) {
                uint32_t ad = s0 + QH_OFF + ((wm * 64 + mt * 16 + (lane & 15)) * 72) * 2
                            + (kc * 2 + lhalf) * 16;
                LDSM_X4(a[mt][0], a[mt][1], a[mt][2], a[mt][3], ad);
            }
            #pragma unroll
            for (int np = 0; np < 2; ++np) {
                uint32_t bd = s0 + KH_OFF + ((wn * 32 + np * 16 + (lane & 15)) * 72) * 2
                            + (kc * 2 + lhalf) * 16;
                uint32_t r0, r1, r2, r3;
                LDSM_X4(r0, r1, r2, r3, bd);
                bfr[np * 2 + 0][0] = r0; bfr[np * 2 + 0][1] = r2;
                bfr[np * 2 + 1][0] = r1; bfr[np * 2 + 1][1] = r3;
            }
            #pragma unroll
            for (int mt = 0; mt < 4; ++mt)
                #pragma unroll
                for (int nt = 0; nt < 4; ++nt)
                    MMAF16(sc[mt][nt][0], sc[mt][nt][1], sc[mt][nt][2], sc[mt][nt][3],
                           a[mt][0], a[mt][1], a[mt][2], a[mt][3],
                           bfr[nt][0], bfr[nt][1]);
        }

        const bool dom = (blockIdx.x == 0) && (t2 == 0);
        #pragma unroll
        for (int mt = 0; mt < 4; ++mt) {
            int r0 = wm * 64 + mt * 16 + (lane >> 2);
            #pragma unroll
            for (int nt = 0; nt < 4; ++nt) {
                int c0 = wn * 32 + nt * 8 + (lane & 3) * 2;
                #pragma unroll
                for (int q = 0; q < 4; ++q) {
                    sc[mt][nt][q] *= 0.125f;
                    if (dom) {
                        int rr = r0 + ((q >= 2) ? 8 : 0);
                        int cc = c0 + (q & 1);
                        if (cc > rr) sc[mt][nt][q] = -1e30f;
                    }
                }
            }
        }

        #pragma unroll
        for (int mt = 0; mt < 4; ++mt) {
            float mlo = -1e30f, mhi = -1e30f;
            #pragma unroll
            for (int nt = 0; nt < 4; ++nt) {
                mlo = fmaxf(mlo, fmaxf(sc[mt][nt][0], sc[mt][nt][1]));
                mhi = fmaxf(mhi, fmaxf(sc[mt][nt][2], sc[mt][nt][3]));
            }
            #pragma unroll
            for (int o = 1; o <= 2; o <<= 1) {
                mlo = fmaxf(mlo, __shfl_xor_sync(0xffffffffu, mlo, o));
                mhi = fmaxf(mhi, __shfl_xor_sync(0xffffffffu, mhi, o));
            }
            if ((lane & 3) == 0) {
                int r0 = wm * 64 + mt * 16 + (lane >> 2);
                redm[wn * 128 + r0] = mlo;
                redm[wn * 128 + r0 + 8] = mhi;
            }
        }
        __syncthreads();

        #pragma unroll
        for (int mt = 0; mt < 4; ++mt) {
            int r0 = wm * 64 + mt * 16 + (lane >> 2);
            float mlo = fmaxf(fmaxf(redm[r0], redm[128 + r0]),
                              fmaxf(redm[256 + r0], redm[384 + r0]));
            int r1 = r0 + 8;
            float mhi = fmaxf(fmaxf(redm[r1], redm[128 + r1]),
                              fmaxf(redm[256 + r1], redm[384 + r1]));
            float slo = 0.f, shi = 0.f;
            #pragma unroll
            for (int nt = 0; nt < 4; ++nt) {
                sc[mt][nt][0] = __expf(sc[mt][nt][0] - mlo);
                sc[mt][nt][1] = __expf(sc[mt][nt][1] - mlo);
                sc[mt][nt][2] = __expf(sc[mt][nt][2] - mhi);
                sc[mt][nt][3] = __expf(sc[mt][nt][3] - mhi);
                slo += sc[mt][nt][0] + sc[mt][nt][1];
                shi += sc[mt][nt][2] + sc[mt][nt][3];
            }
            #pragma unroll
            for (int o = 1; o <= 2; o <<= 1) {
                slo += __shfl_xor_sync(0xffffffffu, slo, o);
                shi += __shfl_xor_sync(0xffffffffu, shi, o);
            }
            if ((lane & 3) == 0) {
                reds[wn * 128 + r0] = slo;
                reds[wn * 128 + r0 + 8] = shi;
            }
        }
        __syncthreads();

        #pragma unroll
        for (int mt = 0; mt < 4; ++mt) {
            int r0 = wm * 64 + mt * 16 + (lane >> 2);
            int r1 = r0 + 8;
            float ilo = __frcp_rn(reds[r0] + reds[128 + r0] + reds[256 + r0] + reds[384 + r0]);
            float ihi = __frcp_rn(reds[r1] + reds[128 + r1] + reds[256 + r1] + reds[384 + r1]);
            #pragma unroll
            for (int nt = 0; nt < 4; ++nt) {
                int c0 = wn * 32 + nt * 8 + (lane & 3) * 2;
                *(__half2*)(sm + PH_OFF + (r0 * 136 + c0) * 2) =
                    __floats2half2_rn(sc[mt][nt][0] * ilo, sc[mt][nt][1] * ilo);
                *(__half2*)(sm + PH_OFF + (r1 * 136 + c0) * 2) =
                    __floats2half2_rn(sc[mt][nt][2] * ihi, sc[mt][nt][3] * ihi);
            }
        }
        __syncthreads();

        float oc[4][2][4];
        #pragma unroll
        for (int i = 0; i < 4; ++i)
            #pragma unroll
            for (int j = 0; j < 2; ++j)
                #pragma unroll
                for (int q = 0; q < 4; ++q) oc[i][j][q] = 0.f;

        #pragma unroll
        for (int kc = 0; kc < 8; ++kc) {
            uint32_t a[4][4], bfr[2][2];
            #pragma unroll
            for (int mt = 0; mt < 4; ++mt) {
                uint32_t ad = s0 + PH_OFF + ((wm * 64 + mt * 16 + (lane & 15)) * 136) * 2
                            + (kc * 2 + lhalf) * 16;
                LDSM_X4(a[mt][0], a[mt][1], a[mt][2], a[mt][3], ad);
            }
            {
                uint32_t bd = s0 + VT_OFF + ((wn * 16 + (lane & 15)) * 136) * 2
                            + (kc * 2 + lhalf) * 16;
                uint32_t r0, r1, r2, r3;
                LDSM_X4(r0, r1, r2, r3, bd);
                bfr[0][0] = r0; bfr[0][1] = r2;
                bfr[1][0] = r1; bfr[1][1] = r3;
            }
            #pragma unroll
            for (int mt = 0; mt < 4; ++mt)
                #pragma unroll
                for (int nt = 0; nt < 2; ++nt)
                    MMAF16(oc[mt][nt][0], oc[mt][nt][1], oc[mt][nt][2], oc[mt][nt][3],
                           a[mt][0], a[mt][1], a[mt][2], a[mt][3],
                           bfr[nt][0], bfr[nt][1]);
        }

        #pragma unroll
        for (int mt = 0; mt < 4; ++mt) {
            int r0 = wm * 64 + mt * 16 + (lane >> 2);
            #pragma unroll
            for (int nt = 0; nt < 2; ++nt) {
                int cd = wn * 16 + nt * 8 + (lane & 3) * 2;
                int gcol = h * HD_ + cd;
                *(__half2*)(As + (size_t)(b * L_ + l0 + r0) * D_ + gcol) =
                    __floats2half2_rn(oc[mt][nt][0], oc[mt][nt][1]);
                *(__half2*)(As + (size_t)(b * L_ + l0 + r0 + 8) * D_ + gcol) =
                    __floats2half2_rn(oc[mt][nt][2], oc[mt][nt][3]);
            }
        }
        __syncthreads();
    }
}

// ===================================================================
extern "C" void kernel_launch(void* const* d_in, const int* in_sizes, int n_in,
                              void* d_out, int out_size)
{
    const float* x   = (const float*)d_in[0];
    const float* fc  = (const float*)d_in[1];
    const float* fs  = (const float*)d_in[2];
    const float* Wq  = (const float*)d_in[3];
    const float* Wk  = (const float*)d_in[4];
    const float* Wv  = (const float*)d_in[5];
    const float* Wo  = (const float*)d_in[6];
    const float* kpm = (const float*)d_in[7];
    const float* vpm = (const float*)d_in[8];
    float* out = (float*)d_out;

    __half *xh, *As, *kvh, *Wq2, *Wkv, *Wo2, *Qh, *Kpp, *Vpp;
    float *KV;
    cudaGetSymbolAddress((void**)&xh,  g_xh);
    cudaGetSymbolAddress((void**)&As,  g_As);
    cudaGetSymbolAddress((void**)&kvh, g_kvh);
    cudaGetSymbolAddress((void**)&Wq2, g_Wq2);
    cudaGetSymbolAddress((void**)&Wkv, g_Wkv);
    cudaGetSymbolAddress((void**)&Wo2, g_Wo2);
    cudaGetSymbolAddress((void**)&Qh,  g_Q);
    cudaGetSymbolAddress((void**)&KV,  g_KV);
    cudaGetSymbolAddress((void**)&Kpp, g_Kp);
    cudaGetSymbolAddress((void**)&Vpp, g_Vp);

    cudaFuncSetAttribute(gemm_f16, cudaFuncAttributeMaxDynamicSharedMemorySize, GEMM_SMEM);
    cudaFuncSetAttribute(attn_mma, cudaFuncAttributeMaxDynamicSharedMemorySize, ATT_SMEM);
    cudaFuncSetAttribute(proj_tc, cudaFuncAttributeMaxDynamicSharedMemorySize, PJ_SMEM);

    // one conversion launch
    conv_all<<<(CONV_TOT + 255) / 256, 256>>>(x, Wq, Wk, Wv, Wo, xh, kvh, Wq2, Wkv, Wo2);

    // Q projection (rope on all tiles, fp16 out)
    gemm_f16<<<dim3(D_ / BN, M_FULL / BM), 256, GEMM_SMEM>>>(
        xh, Wq2, nullptr, Qh, D_, fc, fs, L_ - 1, D_ / BN);

    // fused K+V projection (rope on K half only)
    gemm_f16<<<dim3(2 * D_ / BN, M_KV / BM), 256, GEMM_SMEM>>>(
        kvh, Wkv, KV, nullptr, 2 * D_, fc, fs, P_ - 1, D_ / BN);

    // low-rank projections on tensor cores
    proj_tc<<<dim3(16, B_), 256, PJ_SMEM>>>(KV, kpm, vpm, Kpp, Vpp);

    // attention (4 tiles per CTA)
    attn_mma<<<dim3(L_ / (128 * ATT_TILES), BH_), 256, ATT_SMEM>>>(Qh, Kpp, Vpp, As);

    // final projection (fp32 out)
    gemm_f16<<<dim3(D_ / BN, M_FULL / BM), 256, GEMM_SMEM>>>(
        As, Wo2, out, nullptr, D_, nullptr, nullptr, 0, 0);
}